// round 2
// baseline (speedup 1.0000x reference)
#include <cuda_runtime.h>

#define C_DIM 4096
#define N_F 8
#define NPAIR 36   // 8*9/2, i<=j
#define EPS_F 1e-8f

typedef unsigned long long u64;

// Scratch accumulators (device globals; no allocation allowed).
__device__ float g_rowsum[N_F * C_DIM];   // rowsum[f][u] = sum_v a_f[u,v]
__device__ float g_cross[NPAIR];          // cross[i<=j] = sum_{u,v} a_i a_j

// ---- packed f32x2 helpers (sm_103a) ----
__device__ __forceinline__ u64 pack2(float lo, float hi) {
    u64 r; asm("mov.b64 %0, {%1, %2};" : "=l"(r) : "f"(lo), "f"(hi)); return r;
}
__device__ __forceinline__ void unpack2(float& lo, float& hi, u64 v) {
    asm("mov.b64 {%0, %1}, %2;" : "=f"(lo), "=f"(hi) : "l"(v));
}
__device__ __forceinline__ u64 add2(u64 a, u64 b) {
    u64 d; asm("add.rn.f32x2 %0, %1, %2;" : "=l"(d) : "l"(a), "l"(b)); return d;
}
__device__ __forceinline__ u64 fma2(u64 a, u64 b, u64 c) {
    u64 d; asm("fma.rn.f32x2 %0, %1, %2, %3;" : "=l"(d) : "l"(a), "l"(b), "l"(c)); return d;
}
__device__ __forceinline__ u64 abs2(u64 a) {
    u64 d; asm("and.b64 %0, %1, 0x7FFFFFFF7FFFFFFF;" : "=l"(d) : "l"(a)); return d;
}

__global__ void zero_kernel() {
    int i = blockIdx.x * blockDim.x + threadIdx.x;
    for (; i < N_F * C_DIM; i += gridDim.x * blockDim.x) g_rowsum[i] = 0.0f;
    if (blockIdx.x == 0 && threadIdx.x < NPAIR) g_cross[threadIdx.x] = 0.0f;
}

// Grid: (16 u-tiles of 256, 32 v-chunks of 128). Block: 256 threads.
// Each thread owns one u; processes two v's per iteration with packed f32x2.
// a = |xu - xv|  (sqrt((xu-xv)^2 + 1e-8) ~= |xu-xv|; bias ~1e-5 relative).
__global__ __launch_bounds__(256) void pair_kernel(const float* __restrict__ x) {
    __shared__ u64 shv[N_F][64];              // negated x, [f][vpair], 4 KB
    __shared__ float red[8][NPAIR];           // per-warp cross partials

    const int tid = threadIdx.x;
    const int u = blockIdx.x * 256 + tid;
    const int vbase = blockIdx.y * 128;

    // Load v-chunk of x into shared (negated), layout [f][128] floats.
    {
        float* shf = (float*)shv;
        for (int i = tid; i < 128 * N_F; i += 256) {
            int f = i >> 7;
            int vi = i & 127;
            shf[f * 128 + vi] = -x[f * C_DIM + vbase + vi];
        }
    }

    u64 xu2[N_F];
#pragma unroll
    for (int f = 0; f < N_F; f++) {
        float xu = x[f * C_DIM + u];
        xu2[f] = pack2(xu, xu);
    }

    __syncthreads();

    u64 rs2[N_F];
    u64 acc2[NPAIR];
#pragma unroll
    for (int f = 0; f < N_F; f++) rs2[f] = 0ull;
#pragma unroll
    for (int k = 0; k < NPAIR; k++) acc2[k] = 0ull;

#pragma unroll 4
    for (int vp = 0; vp < 64; vp++) {
        u64 a2[N_F];
#pragma unroll
        for (int f = 0; f < N_F; f++) {
            u64 nv = shv[f][vp];            // broadcast LDS.64 (negated pair)
            u64 d  = add2(xu2[f], nv);      // xu - xv  (two v's packed)
            u64 ab = abs2(d);               // |d| = a
            a2[f]  = ab;
            rs2[f] = add2(rs2[f], ab);
        }
        int k = 0;
#pragma unroll
        for (int i = 0; i < N_F; i++) {
#pragma unroll
            for (int j = i; j < N_F; j++) {
                acc2[k] = fma2(a2[i], a2[j], acc2[k]);
                k++;
            }
        }
    }

    // Collapse packed lanes.
    float rs[N_F];
    float acc[NPAIR];
#pragma unroll
    for (int f = 0; f < N_F; f++) {
        float lo, hi; unpack2(lo, hi, rs2[f]);
        rs[f] = lo + hi;
    }
#pragma unroll
    for (int k = 0; k < NPAIR; k++) {
        float lo, hi; unpack2(lo, hi, acc2[k]);
        acc[k] = lo + hi;
    }

    // Row sums: u unique within block; accumulate across v-chunks via atomics.
#pragma unroll
    for (int f = 0; f < N_F; f++) atomicAdd(&g_rowsum[f * C_DIM + u], rs[f]);

    // Block-reduce the 36 cross accumulators, then one atomic per value.
    const int lane = tid & 31;
    const int warp = tid >> 5;
#pragma unroll
    for (int k = 0; k < NPAIR; k++) {
        float v = acc[k];
        for (int o = 16; o; o >>= 1) v += __shfl_down_sync(0xffffffffu, v, o);
        if (lane == 0) red[warp][k] = v;
    }
    __syncthreads();
    if (warp == 0) {
        for (int k = lane; k < NPAIR; k += 32) {
            float v = 0.0f;
#pragma unroll
            for (int w = 0; w < 8; w++) v += red[w][k];
            atomicAdd(&g_cross[k], v);
        }
    }
}

// Single block: 36 rowsum dot products + dcov/ratio math.
__global__ __launch_bounds__(256) void finalize_kernel(float* __restrict__ out) {
    const int tid = threadIdx.x;
    float dot[NPAIR];
    float ssum[N_F];
#pragma unroll
    for (int k = 0; k < NPAIR; k++) dot[k] = 0.0f;
#pragma unroll
    for (int f = 0; f < N_F; f++) ssum[f] = 0.0f;

    for (int u = tid; u < C_DIM; u += 256) {
        float r[N_F];
#pragma unroll
        for (int f = 0; f < N_F; f++) {
            r[f] = g_rowsum[f * C_DIM + u];
            ssum[f] += r[f];
        }
        int k = 0;
#pragma unroll
        for (int i = 0; i < N_F; i++) {
#pragma unroll
            for (int j = i; j < N_F; j++) {
                dot[k] = fmaf(r[i], r[j], dot[k]);
                k++;
            }
        }
    }

    __shared__ float stot[NPAIR + N_F];
    if (tid < NPAIR + N_F) stot[tid] = 0.0f;
    __syncthreads();

    const int lane = tid & 31;
#pragma unroll
    for (int k = 0; k < NPAIR; k++) {
        float v = dot[k];
        for (int o = 16; o; o >>= 1) v += __shfl_down_sync(0xffffffffu, v, o);
        if (lane == 0) atomicAdd(&stot[k], v);
    }
#pragma unroll
    for (int f = 0; f < N_F; f++) {
        float v = ssum[f];
        for (int o = 16; o; o >>= 1) v += __shfl_down_sync(0xffffffffu, v, o);
        if (lane == 0) atomicAdd(&stot[NPAIR + f], v);
    }
    __syncthreads();

    if (tid == 0) {
        const float fC = (float)C_DIM;
        const float invC2 = 1.0f / (fC * fC);

        float m[N_F];
#pragma unroll
        for (int f = 0; f < N_F; f++) m[f] = stot[NPAIR + f] * invC2;

        // S[i][j] = cross/C^2 - 2*(rowsum_i . rowsum_j)/C^3 + m_i*m_j
        float dcov[N_F][N_F];
        int k = 0;
        for (int i = 0; i < N_F; i++) {
            for (int j = i; j < N_F; j++) {
                float s = g_cross[k] * invC2
                        - 2.0f * stot[k] * invC2 / fC
                        + m[i] * m[j];
                float dc = sqrtf(fmaxf(s, 0.0f) + EPS_F);
                dcov[i][j] = dc;
                dcov[j][i] = dc;
                k++;
            }
        }

        float cor = 0.0f;
        for (int i = 0; i < N_F; i++)
            for (int j = i + 1; j < N_F; j++)
                cor += dcov[i][j] / sqrtf(dcov[i][i] * dcov[j][j] + EPS_F);

        out[0] = cor;
    }
}

extern "C" void kernel_launch(void* const* d_in, const int* in_sizes, int n_in,
                              void* d_out, int out_size) {
    const float* x = (const float*)d_in[0];
    float* out = (float*)d_out;

    zero_kernel<<<32, 256>>>();
    pair_kernel<<<dim3(16, 32), 256>>>(x);
    finalize_kernel<<<1, 256>>>(out);
}

// round 3
// speedup vs baseline: 1.6448x; 1.6448x over previous
#include <cuda_runtime.h>

#define C_DIM 4096
#define N_F 8
#define NPAIR 36            // 8*9/2, i<=j
#define EPS_F 1e-8f
#define NTILE 32            // 4096 / 128
#define NCROSS 528          // NTILE*(NTILE+1)/2 triangle tiles
#define NROWB 256           // 8 factors * 32 u-tiles of 128
#define NBLOCKS (NCROSS + NROWB)

typedef unsigned long long u64;

// Scratch (device globals; no allocation allowed). Fully overwritten each call.
__device__ float g_rowsum[N_F * C_DIM];      // rowsum[f][u] = sum_v |x_fu - x_fv|
__device__ float g_parts[NCROSS][NPAIR];     // per-tile cross partials (u<v pairs)

// ---- packed f32x2 helpers (used ONLY in the register-light rowsum path) ----
__device__ __forceinline__ u64 pack2(float lo, float hi) {
    u64 r; asm("mov.b64 %0, {%1, %2};" : "=l"(r) : "f"(lo), "f"(hi)); return r;
}
__device__ __forceinline__ void unpack2(float& lo, float& hi, u64 v) {
    asm("mov.b64 {%0, %1}, %2;" : "=f"(lo), "=f"(hi) : "l"(v));
}
__device__ __forceinline__ u64 add2(u64 a, u64 b) {
    u64 d; asm("add.rn.f32x2 %0, %1, %2;" : "=l"(d) : "l"(a), "l"(b)); return d;
}
__device__ __forceinline__ u64 abs2(u64 a) {
    u64 d; asm("and.b64 %0, %1, 0x7FFFFFFF7FFFFFFF;" : "=l"(d) : "l"(a)); return d;
}

// One kernel, two block roles:
//  blocks [0, 528):      cross-product tiles over the upper triangle (scalar FFMA)
//  blocks [528, 784):    rowsum rows (packed f32x2, register-light)
__global__ __launch_bounds__(128) void main_kernel(const float* __restrict__ x) {
    __shared__ union {
        struct {
            float v[128][N_F];      // v-tile values [vi][f], 4 KB
            float red[4][NPAIR];    // per-warp cross partials
        } c;
        u64 row[C_DIM / 2];         // negated full row for rowsum path, 16 KB
    } sh;

    const int tid = threadIdx.x;

    if (blockIdx.x < NCROSS) {
        // ---------------- cross path: tile (ti, tj), ti <= tj ----------------
        int rem = blockIdx.x, ti = 0;
        while (rem >= NTILE - ti) { rem -= NTILE - ti; ti++; }
        const int tj = ti + rem;

        // Load v-tile into shared: [vi][f] layout (float4-readable).
        for (int i = tid; i < 128 * N_F; i += 128) {
            int f = i >> 7, vi = i & 127;
            sh.c.v[vi][f] = x[f * C_DIM + tj * 128 + vi];
        }

        const int u = ti * 128 + tid;
        float xu[N_F];
#pragma unroll
        for (int f = 0; f < N_F; f++) xu[f] = x[f * C_DIM + u];

        __syncthreads();

        float acc[NPAIR];
#pragma unroll
        for (int k = 0; k < NPAIR; k++) acc[k] = 0.0f;

#pragma unroll 2
        for (int vi = 0; vi < 128; vi++) {
            float4 p0 = *reinterpret_cast<const float4*>(&sh.c.v[vi][0]);
            float4 p1 = *reinterpret_cast<const float4*>(&sh.c.v[vi][4]);
            float xv[N_F] = {p0.x, p0.y, p0.z, p0.w, p1.x, p1.y, p1.z, p1.w};

            float a[N_F];
#pragma unroll
            for (int f = 0; f < N_F; f++) a[f] = fabsf(xu[f] - xv[f]);

            int k = 0;
#pragma unroll
            for (int i = 0; i < N_F; i++) {
#pragma unroll
                for (int j = i; j < N_F; j++) {
                    acc[k] = fmaf(a[i], a[j], acc[k]);
                    k++;
                }
            }
        }

        // Diagonal tiles are internally symmetric: weight 0.5 so every
        // unordered pair u<v is counted exactly once across all tiles.
        const float w = (ti == tj) ? 0.5f : 1.0f;

        const int lane = tid & 31;
        const int warp = tid >> 5;
#pragma unroll
        for (int k = 0; k < NPAIR; k++) {
            float v = acc[k];
            for (int o = 16; o; o >>= 1) v += __shfl_down_sync(0xffffffffu, v, o);
            if (lane == 0) sh.c.red[warp][k] = v * w;
        }
        __syncthreads();
        if (tid < NPAIR) {
            g_parts[blockIdx.x][tid] =
                sh.c.red[0][tid] + sh.c.red[1][tid] + sh.c.red[2][tid] + sh.c.red[3][tid];
        }
    } else {
        // ---------------- rowsum path: one (f, u) per thread ----------------
        const int rb = blockIdx.x - NCROSS;
        const int f = rb >> 5;            // 0..7
        const int ut = rb & 31;           // u-tile of 128
        const float* xf = x + f * C_DIM;

        // Load full negated row into shared (so diff = add2).
        float* rowf = (float*)sh.row;
        for (int i = tid; i < C_DIM; i += 128) rowf[i] = -xf[i];

        const int u = ut * 128 + tid;
        const float xu = xf[u];
        const u64 xu2 = pack2(xu, xu);

        __syncthreads();

        u64 s0 = 0ull, s1 = 0ull, s2 = 0ull, s3 = 0ull;
#pragma unroll 4
        for (int p = 0; p < C_DIM / 2; p += 4) {
            s0 = add2(s0, abs2(add2(xu2, sh.row[p + 0])));
            s1 = add2(s1, abs2(add2(xu2, sh.row[p + 1])));
            s2 = add2(s2, abs2(add2(xu2, sh.row[p + 2])));
            s3 = add2(s3, abs2(add2(xu2, sh.row[p + 3])));
        }
        float a0, b0, a1, b1, a2, b2, a3, b3;
        unpack2(a0, b0, s0); unpack2(a1, b1, s1);
        unpack2(a2, b2, s2); unpack2(a3, b3, s3);
        g_rowsum[f * C_DIM + u] = ((a0 + b0) + (a1 + b1)) + ((a2 + b2) + (a3 + b3));
    }
}

// Single block: reduce g_parts, rowsum dot products, dcov/ratio math.
__global__ __launch_bounds__(256) void finalize_kernel(float* __restrict__ out) {
    const int tid = threadIdx.x;
    const int lane = tid & 31;

    float dot[NPAIR], cl[NPAIR], ssum[N_F];
#pragma unroll
    for (int k = 0; k < NPAIR; k++) { dot[k] = 0.0f; cl[k] = 0.0f; }
#pragma unroll
    for (int f = 0; f < N_F; f++) ssum[f] = 0.0f;

    // Rowsum dots + totals.
    for (int u = tid; u < C_DIM; u += 256) {
        float r[N_F];
#pragma unroll
        for (int f = 0; f < N_F; f++) {
            r[f] = g_rowsum[f * C_DIM + u];
            ssum[f] += r[f];
        }
        int k = 0;
#pragma unroll
        for (int i = 0; i < N_F; i++)
#pragma unroll
            for (int j = i; j < N_F; j++) {
                dot[k] = fmaf(r[i], r[j], dot[k]);
                k++;
            }
    }

    // Cross partial reduction.
    for (int b = tid; b < NCROSS; b += 256) {
#pragma unroll
        for (int k = 0; k < NPAIR; k++) cl[k] += g_parts[b][k];
    }

    __shared__ float stot[2 * NPAIR + N_F];   // [0,36): dots  [36,72): cross  [72,80): sums
    if (tid < 2 * NPAIR + N_F) stot[tid] = 0.0f;
    __syncthreads();

#pragma unroll
    for (int k = 0; k < NPAIR; k++) {
        float v = dot[k];
        for (int o = 16; o; o >>= 1) v += __shfl_down_sync(0xffffffffu, v, o);
        if (lane == 0) atomicAdd(&stot[k], v);
    }
#pragma unroll
    for (int k = 0; k < NPAIR; k++) {
        float v = cl[k];
        for (int o = 16; o; o >>= 1) v += __shfl_down_sync(0xffffffffu, v, o);
        if (lane == 0) atomicAdd(&stot[NPAIR + k], v);
    }
#pragma unroll
    for (int f = 0; f < N_F; f++) {
        float v = ssum[f];
        for (int o = 16; o; o >>= 1) v += __shfl_down_sync(0xffffffffu, v, o);
        if (lane == 0) atomicAdd(&stot[2 * NPAIR + f], v);
    }
    __syncthreads();

    if (tid == 0) {
        const float fC = (float)C_DIM;
        const float invC2 = 1.0f / (fC * fC);

        float m[N_F];
#pragma unroll
        for (int f = 0; f < N_F; f++) m[f] = stot[2 * NPAIR + f] * invC2;

        // S[i][j] = 2*cross_tri/C^2 - 2*rowdot/C^3 + m_i*m_j
        float dcov[N_F][N_F];
        int k = 0;
        for (int i = 0; i < N_F; i++) {
            for (int j = i; j < N_F; j++) {
                float s = 2.0f * stot[NPAIR + k] * invC2
                        - 2.0f * stot[k] * invC2 / fC
                        + m[i] * m[j];
                float dc = sqrtf(fmaxf(s, 0.0f) + EPS_F);
                dcov[i][j] = dc;
                dcov[j][i] = dc;
                k++;
            }
        }

        float cor = 0.0f;
        for (int i = 0; i < N_F; i++)
            for (int j = i + 1; j < N_F; j++)
                cor += dcov[i][j] / sqrtf(dcov[i][i] * dcov[j][j] + EPS_F);

        out[0] = cor;
    }
}

extern "C" void kernel_launch(void* const* d_in, const int* in_sizes, int n_in,
                              void* d_out, int out_size) {
    const float* x = (const float*)d_in[0];
    float* out = (float*)d_out;

    main_kernel<<<NBLOCKS, 128>>>(x);
    finalize_kernel<<<1, 256>>>(out);
}

// round 4
// speedup vs baseline: 2.1964x; 1.3353x over previous
#include <cuda_runtime.h>

#define C_DIM 4096
#define N_F 8
#define NPAIR 36            // 8*9/2, i<=j
#define EPS_F 1e-8f
#define NTILE 32            // 4096 / 128
#define NCROSS 528          // NTILE*(NTILE+1)/2 triangle tiles
#define NROWB 256           // 8 factors * 32 u-tiles of 128
#define NBLOCKS (NCROSS + NROWB)
#define NSTOT (2 * NPAIR + N_F)   // [0,36): rowdots  [36,72): cross  [72,80): sums

typedef unsigned long long u64;

// Scratch (device globals; no allocation allowed). Fully overwritten each call.
__device__ float g_rowsum[N_F * C_DIM];      // rowsum[f][u] = sum_v |x_fu - x_fv|
__device__ float g_parts[NCROSS][NPAIR];     // per-tile cross partials (u<v pairs)
__device__ float g_stot[NSTOT];              // global accumulators for reduce

// ---- packed f32x2 helpers (used ONLY in the register-light rowsum path) ----
__device__ __forceinline__ u64 pack2(float lo, float hi) {
    u64 r; asm("mov.b64 %0, {%1, %2};" : "=l"(r) : "f"(lo), "f"(hi)); return r;
}
__device__ __forceinline__ void unpack2(float& lo, float& hi, u64 v) {
    asm("mov.b64 {%0, %1}, %2;" : "=f"(lo), "=f"(hi) : "l"(v));
}
__device__ __forceinline__ u64 add2(u64 a, u64 b) {
    u64 d; asm("add.rn.f32x2 %0, %1, %2;" : "=l"(d) : "l"(a), "l"(b)); return d;
}
__device__ __forceinline__ u64 abs2(u64 a) {
    u64 d; asm("and.b64 %0, %1, 0x7FFFFFFF7FFFFFFF;" : "=l"(d) : "l"(a)); return d;
}

// One kernel, two block roles:
//  blocks [0, 528):      cross-product tiles over the upper triangle (scalar FFMA)
//  blocks [528, 784):    rowsum rows (packed f32x2, register-light)
__global__ __launch_bounds__(128) void main_kernel(const float* __restrict__ x) {
    __shared__ union {
        struct {
            float v[128][N_F];      // v-tile values [vi][f], 4 KB
            float red[4][NPAIR];    // per-warp cross partials
        } c;
        u64 row[C_DIM / 2];         // negated full row for rowsum path, 16 KB
    } sh;

    const int tid = threadIdx.x;

    // Block 0 zeroes the global accumulators used by the later reduce kernel.
    if (blockIdx.x == 0 && tid < NSTOT) g_stot[tid] = 0.0f;

    if (blockIdx.x < NCROSS) {
        // ---------------- cross path: tile (ti, tj), ti <= tj ----------------
        int rem = blockIdx.x, ti = 0;
        while (rem >= NTILE - ti) { rem -= NTILE - ti; ti++; }
        const int tj = ti + rem;

        // Load v-tile into shared: [vi][f] layout (float4-readable).
        for (int i = tid; i < 128 * N_F; i += 128) {
            int f = i >> 7, vi = i & 127;
            sh.c.v[vi][f] = x[f * C_DIM + tj * 128 + vi];
        }

        const int u = ti * 128 + tid;
        float xu[N_F];
#pragma unroll
        for (int f = 0; f < N_F; f++) xu[f] = x[f * C_DIM + u];

        __syncthreads();

        float acc[NPAIR];
#pragma unroll
        for (int k = 0; k < NPAIR; k++) acc[k] = 0.0f;

#pragma unroll 2
        for (int vi = 0; vi < 128; vi++) {
            float4 p0 = *reinterpret_cast<const float4*>(&sh.c.v[vi][0]);
            float4 p1 = *reinterpret_cast<const float4*>(&sh.c.v[vi][4]);
            float xv[N_F] = {p0.x, p0.y, p0.z, p0.w, p1.x, p1.y, p1.z, p1.w};

            float a[N_F];
#pragma unroll
            for (int f = 0; f < N_F; f++) a[f] = fabsf(xu[f] - xv[f]);

            int k = 0;
#pragma unroll
            for (int i = 0; i < N_F; i++) {
#pragma unroll
                for (int j = i; j < N_F; j++) {
                    acc[k] = fmaf(a[i], a[j], acc[k]);
                    k++;
                }
            }
        }

        // Diagonal tiles are internally symmetric: weight 0.5 so every
        // unordered pair u<v is counted exactly once across all tiles.
        const float w = (ti == tj) ? 0.5f : 1.0f;

        const int lane = tid & 31;
        const int warp = tid >> 5;
#pragma unroll
        for (int k = 0; k < NPAIR; k++) {
            float v = acc[k];
            for (int o = 16; o; o >>= 1) v += __shfl_down_sync(0xffffffffu, v, o);
            if (lane == 0) sh.c.red[warp][k] = v * w;
        }
        __syncthreads();
        if (tid < NPAIR) {
            g_parts[blockIdx.x][tid] =
                sh.c.red[0][tid] + sh.c.red[1][tid] + sh.c.red[2][tid] + sh.c.red[3][tid];
        }
    } else {
        // ---------------- rowsum path: one (f, u) per thread ----------------
        const int rb = blockIdx.x - NCROSS;
        const int f = rb >> 5;            // 0..7
        const int ut = rb & 31;           // u-tile of 128
        const float* xf = x + f * C_DIM;

        // Load full negated row into shared (so diff = add2).
        float* rowf = (float*)sh.row;
        for (int i = tid; i < C_DIM; i += 128) rowf[i] = -xf[i];

        const int u = ut * 128 + tid;
        const float xu = xf[u];
        const u64 xu2 = pack2(xu, xu);

        __syncthreads();

        u64 s0 = 0ull, s1 = 0ull, s2 = 0ull, s3 = 0ull;
#pragma unroll 4
        for (int p = 0; p < C_DIM / 2; p += 4) {
            s0 = add2(s0, abs2(add2(xu2, sh.row[p + 0])));
            s1 = add2(s1, abs2(add2(xu2, sh.row[p + 1])));
            s2 = add2(s2, abs2(add2(xu2, sh.row[p + 2])));
            s3 = add2(s3, abs2(add2(xu2, sh.row[p + 3])));
        }
        float a0, b0, a1, b1, a2, b2, a3, b3;
        unpack2(a0, b0, s0); unpack2(a1, b1, s1);
        unpack2(a2, b2, s2); unpack2(a3, b3, s3);
        g_rowsum[f * C_DIM + u] = ((a0 + b0) + (a1 + b1)) + ((a2 + b2) + (a3 + b3));
    }
}

// Parallel epilogue reduction: 17 blocks.
//  blocks [0, 16): rowsum dots + factor sums over 256 u's each
//  block 16:       g_parts cross reduction
__global__ __launch_bounds__(256) void reduce_kernel() {
    __shared__ float red[8][NPAIR + N_F];
    const int tid = threadIdx.x;
    const int lane = tid & 31;
    const int warp = tid >> 5;

    if (blockIdx.x < 16) {
        const int u = blockIdx.x * 256 + tid;
        float r[N_F];
        float ssum_part;
        float dot[NPAIR];
#pragma unroll
        for (int f = 0; f < N_F; f++) r[f] = g_rowsum[f * C_DIM + u];
        int k = 0;
#pragma unroll
        for (int i = 0; i < N_F; i++)
#pragma unroll
            for (int j = i; j < N_F; j++) {
                dot[k] = r[i] * r[j];
                k++;
            }

        // warp-reduce 36 dots + 8 sums
#pragma unroll
        for (int kk = 0; kk < NPAIR; kk++) {
            float v = dot[kk];
            for (int o = 16; o; o >>= 1) v += __shfl_down_sync(0xffffffffu, v, o);
            if (lane == 0) red[warp][kk] = v;
        }
#pragma unroll
        for (int f = 0; f < N_F; f++) {
            float v = r[f];
            for (int o = 16; o; o >>= 1) v += __shfl_down_sync(0xffffffffu, v, o);
            if (lane == 0) red[warp][NPAIR + f] = v;
        }
        __syncthreads();
        for (int kk = tid; kk < NPAIR + N_F; kk += 256) {
            float v = 0.0f;
#pragma unroll
            for (int w = 0; w < 8; w++) v += red[w][kk];
            int dst = (kk < NPAIR) ? kk : (NPAIR + kk);   // dots->[0,36), sums->[72,80)
            atomicAdd(&g_stot[dst], v);
        }
        (void)ssum_part;
    } else {
        // cross partials: 528 rows x 36
        float cl[NPAIR];
#pragma unroll
        for (int kk = 0; kk < NPAIR; kk++) cl[kk] = 0.0f;
        for (int b = tid; b < NCROSS; b += 256) {
#pragma unroll
            for (int kk = 0; kk < NPAIR; kk++) cl[kk] += g_parts[b][kk];
        }
#pragma unroll
        for (int kk = 0; kk < NPAIR; kk++) {
            float v = cl[kk];
            for (int o = 16; o; o >>= 1) v += __shfl_down_sync(0xffffffffu, v, o);
            if (lane == 0) red[warp][kk] = v;
        }
        __syncthreads();
        if (tid < NPAIR) {
            float v = 0.0f;
#pragma unroll
            for (int w = 0; w < 8; w++) v += red[w][tid];
            atomicAdd(&g_stot[NPAIR + tid], v);
        }
    }
}

// Tiny scalar epilogue: 8x8 dcov/ratio math.
__global__ void final_kernel(float* __restrict__ out) {
    if (threadIdx.x != 0) return;

    const float fC = (float)C_DIM;
    const float invC2 = 1.0f / (fC * fC);

    float m[N_F];
#pragma unroll
    for (int f = 0; f < N_F; f++) m[f] = g_stot[2 * NPAIR + f] * invC2;

    // S[i][j] = 2*cross_tri/C^2 - 2*rowdot/C^3 + m_i*m_j
    float dcov[N_F][N_F];
    int k = 0;
    for (int i = 0; i < N_F; i++) {
        for (int j = i; j < N_F; j++) {
            float s = 2.0f * g_stot[NPAIR + k] * invC2
                    - 2.0f * g_stot[k] * invC2 / fC
                    + m[i] * m[j];
            float dc = sqrtf(fmaxf(s, 0.0f) + EPS_F);
            dcov[i][j] = dc;
            dcov[j][i] = dc;
            k++;
        }
    }

    float cor = 0.0f;
    for (int i = 0; i < N_F; i++)
        for (int j = i + 1; j < N_F; j++)
            cor += dcov[i][j] / sqrtf(dcov[i][i] * dcov[j][j] + EPS_F);

    out[0] = cor;
}

extern "C" void kernel_launch(void* const* d_in, const int* in_sizes, int n_in,
                              void* d_out, int out_size) {
    const float* x = (const float*)d_in[0];
    float* out = (float*)d_out;

    main_kernel<<<NBLOCKS, 128>>>(x);
    reduce_kernel<<<17, 256>>>();
    final_kernel<<<1, 32>>>(out);
}